// round 1
// baseline (speedup 1.0000x reference)
#include <cuda_runtime.h>

// Problem constants (fixed shapes)
#define Bz 32768
#define Dd 2048
#define Ld 64
#define NC 64   // SOM_H * SOM_W

// Scratch (no allocations allowed)
static __device__ float g_Cq[NC * Dd];   // E @ W_dec_q + b_dec_q  (512 KB)
static __device__ float g_Esq[NC];       // sum(E^2) per code
static __device__ int   g_k[Bz];         // argmin indices

// ---------------------------------------------------------------------------
// K0: precompute C_q[c][d] = sum_l E[c][l]*W_dec_q[l][d] + b_dec_q[d], and E^2
// grid 64 (one block per code), 256 threads
// ---------------------------------------------------------------------------
__global__ void k_precompute(const float* __restrict__ E,
                             const float* __restrict__ Wdq,
                             const float* __restrict__ bdq) {
    __shared__ float Es[Ld];
    int c = blockIdx.x;
    if (threadIdx.x < Ld) Es[threadIdx.x] = E[c * Ld + threadIdx.x];
    __syncthreads();
    for (int d = threadIdx.x; d < Dd; d += blockDim.x) {
        float acc = bdq[d];
#pragma unroll
        for (int l = 0; l < Ld; l++) acc = fmaf(Es[l], Wdq[l * Dd + d], acc);
        g_Cq[c * Dd + d] = acc;
    }
    if (threadIdx.x == 0) {
        float s = 0.f;
#pragma unroll
        for (int l = 0; l < Ld; l++) s = fmaf(Es[l], Es[l], s);
        g_Esq[c] = s;
    }
}

// ---------------------------------------------------------------------------
// K1: z_e = x @ W_enc + b_enc     [32768,2048] x [2048,64] -> [32768,64]
// Block tile: 64 rows x 64 cols, K-chunk 32. 256 threads, 4x4 per thread.
// grid Bz/64 = 512
// ---------------------------------------------------------------------------
__global__ __launch_bounds__(256) void k_enc(const float* __restrict__ x,
                                             const float* __restrict__ Wenc,
                                             const float* __restrict__ benc,
                                             float* __restrict__ ze) {
    __shared__ float xs[64][33];   // +1 pad kills bank conflicts on a-reads
    __shared__ float ws[32][64];
    int tid = threadIdx.x;
    int tx = tid & 15, ty = tid >> 4;
    int row0 = blockIdx.x * 64;
    float acc[4][4] = {};

    for (int k0 = 0; k0 < Dd; k0 += 32) {
#pragma unroll
        for (int i = 0; i < 2; i++) {          // x tile: 64x32 = 512 float4
            int idx = tid + i * 256;
            int r = idx >> 3, c4 = idx & 7;
            float4 v = *(const float4*)&x[(size_t)(row0 + r) * Dd + k0 + c4 * 4];
            xs[r][c4 * 4 + 0] = v.x; xs[r][c4 * 4 + 1] = v.y;
            xs[r][c4 * 4 + 2] = v.z; xs[r][c4 * 4 + 3] = v.w;
        }
#pragma unroll
        for (int i = 0; i < 2; i++) {          // W tile: 32x64 = 512 float4
            int idx = tid + i * 256;
            int r = idx >> 4, c4 = idx & 15;
            *(float4*)&ws[r][c4 * 4] =
                *(const float4*)&Wenc[(size_t)(k0 + r) * Ld + c4 * 4];
        }
        __syncthreads();
#pragma unroll
        for (int kk = 0; kk < 32; kk++) {
            float a[4];
#pragma unroll
            for (int r = 0; r < 4; r++) a[r] = xs[ty * 4 + r][kk];
            float4 b4 = *(float4*)&ws[kk][tx * 4];
            float b[4] = {b4.x, b4.y, b4.z, b4.w};
#pragma unroll
            for (int r = 0; r < 4; r++)
#pragma unroll
                for (int c = 0; c < 4; c++)
                    acc[r][c] = fmaf(a[r], b[c], acc[r][c]);
        }
        __syncthreads();
    }
    float4 bb = *(const float4*)&benc[tx * 4];
#pragma unroll
    for (int r = 0; r < 4; r++) {
        float4 o = make_float4(acc[r][0] + bb.x, acc[r][1] + bb.y,
                               acc[r][2] + bb.z, acc[r][3] + bb.w);
        *(float4*)&ze[(size_t)(row0 + ty * 4 + r) * Ld + tx * 4] = o;
    }
}

// ---------------------------------------------------------------------------
// K_assign: distances, argmin, z_q, neighbors, k, z_dist_flat
// one thread per row; grid Bz/256 = 128
// ---------------------------------------------------------------------------
__global__ __launch_bounds__(256) void k_assign(const float* __restrict__ ze,
                                                const float* __restrict__ E,
                                                float* __restrict__ zq,
                                                float* __restrict__ nb,
                                                float* __restrict__ kout,
                                                float* __restrict__ zdist) {
    __shared__ float Es[NC][Ld];     // 16 KB
    __shared__ float Esq_s[NC];
    int tid = threadIdx.x;
#pragma unroll
    for (int i = 0; i < 4; i++) {
        int idx = tid + i * 256;     // 1024 float4 total
        ((float4*)Es)[idx] = ((const float4*)E)[idx];
    }
    if (tid < NC) Esq_s[tid] = g_Esq[tid];
    __syncthreads();

    int row = blockIdx.x * 256 + tid;
    const float* zr = ze + (size_t)row * Ld;
    float4 z4[16];
#pragma unroll
    for (int j = 0; j < 16; j++) z4[j] = *(const float4*)&zr[j * 4];
    float ze2 = 0.f;
#pragma unroll
    for (int j = 0; j < 16; j++) {
        ze2 = fmaf(z4[j].x, z4[j].x, ze2);
        ze2 = fmaf(z4[j].y, z4[j].y, ze2);
        ze2 = fmaf(z4[j].z, z4[j].z, ze2);
        ze2 = fmaf(z4[j].w, z4[j].w, ze2);
    }

    float best = 3.4e38f; int bk = 0;
    float* zd = zdist + (size_t)row * NC;
    for (int c0 = 0; c0 < NC; c0 += 4) {
        float dvals[4];
#pragma unroll
        for (int u = 0; u < 4; u++) {
            int c = c0 + u;
            float dot = 0.f;
#pragma unroll
            for (int j = 0; j < 16; j++) {
                float4 e = *(const float4*)&Es[c][j * 4];
                dot = fmaf(z4[j].x, e.x, dot);
                dot = fmaf(z4[j].y, e.y, dot);
                dot = fmaf(z4[j].z, e.z, dot);
                dot = fmaf(z4[j].w, e.w, dot);
            }
            float dcur = ze2 - 2.f * dot + Esq_s[c];
            dvals[u] = dcur;
            if (dcur < best) { best = dcur; bk = c; }  // strict < => first min (jnp.argmin)
        }
        *(float4*)&zd[c0] = make_float4(dvals[0], dvals[1], dvals[2], dvals[3]);
    }

    kout[row] = (float)bk;
    g_k[row] = bk;
    int k1 = bk >> 3, k2 = bk & 7;

    float* zqr = zq + (size_t)row * Ld;
    float* nbr = nb + (size_t)row * 5 * Ld;
    const float4* eb = (const float4*)&Es[bk][0];
#pragma unroll
    for (int j = 0; j < 16; j++) {
        float4 v = eb[j];
        *(float4*)&zqr[j * 4] = v;          // z_q
        *(float4*)&nbr[j * 4] = v;          // neighbor slot 0 = z_q
    }
    const float4 zero4 = make_float4(0.f, 0.f, 0.f, 0.f);
    {   // up: k_1 < 7 ? E[k1+1][k2] : 0
        bool ok = (k1 < 7); int idx = ok ? ((k1 + 1) * 8 + k2) : 0;
        const float4* e = (const float4*)&Es[idx][0];
#pragma unroll
        for (int j = 0; j < 16; j++) *(float4*)&nbr[64 + j * 4] = ok ? e[j] : zero4;
    }
    {   // down: k_1 > 0 ? E[k1-1][k2] : 0
        bool ok = (k1 > 0); int idx = ok ? ((k1 - 1) * 8 + k2) : 0;
        const float4* e = (const float4*)&Es[idx][0];
#pragma unroll
        for (int j = 0; j < 16; j++) *(float4*)&nbr[128 + j * 4] = ok ? e[j] : zero4;
    }
    {   // right: always zero (faithful to reference's `==` bug)
#pragma unroll
        for (int j = 0; j < 16; j++) *(float4*)&nbr[192 + j * 4] = zero4;
    }
    {   // left: k_2 > 0 ? E[k1][k2-1] : 0
        bool ok = (k2 > 0); int idx = ok ? (k1 * 8 + k2 - 1) : 0;
        const float4* e = (const float4*)&Es[idx][0];
#pragma unroll
        for (int j = 0; j < 16; j++) *(float4*)&nbr[256 + j * 4] = ok ? e[j] : zero4;
    }
}

// ---------------------------------------------------------------------------
// K3: x_q[i] = C_q[k[i]]   pure gather-write of float4
// grid 65536, 256 threads
// ---------------------------------------------------------------------------
__global__ void k_xq(float* __restrict__ xq) {
    int idx = blockIdx.x * 256 + threadIdx.x;  // < Bz*Dd/4
    int row = idx >> 9;                        // Dd/4 = 512
    int c4 = idx & 511;
    int kk = g_k[row];
    ((float4*)xq)[idx] = ((const float4*)g_Cq)[(size_t)kk * 512 + c4];
}

// ---------------------------------------------------------------------------
// K2: x_e = z_e @ W_dec_e + b_dec_e    [32768,64] x [64,2048]
// Block tile: 128 rows x 64 cols, full K=64 in one pass. 8x4 per thread.
// grid (Bz/128, Dd/64) = (256, 32)
// ---------------------------------------------------------------------------
__global__ __launch_bounds__(256) void k_dec(const float* __restrict__ ze,
                                             const float* __restrict__ Wde,
                                             const float* __restrict__ bde,
                                             float* __restrict__ xe) {
    __shared__ float As[128][64];   // 32 KB (unpadded: 2-way LDS conflict, acceptable)
    __shared__ float Bs[64][64];    // 16 KB  -> total 48 KB exactly
    int tid = threadIdx.x;
    int tx = tid & 15, ty = tid >> 4;
    int row0 = blockIdx.x * 128, col0 = blockIdx.y * 64;

#pragma unroll
    for (int i = 0; i < 8; i++) {           // A: 128x64 = 2048 float4
        int idx = tid + i * 256;
        int r = idx >> 4, c4 = idx & 15;
        *(float4*)&As[r][c4 * 4] = *(const float4*)&ze[(size_t)(row0 + r) * Ld + c4 * 4];
    }
#pragma unroll
    for (int i = 0; i < 4; i++) {           // B: 64x64 = 1024 float4
        int idx = tid + i * 256;
        int r = idx >> 4, c4 = idx & 15;
        *(float4*)&Bs[r][c4 * 4] = *(const float4*)&Wde[(size_t)r * Dd + col0 + c4 * 4];
    }
    __syncthreads();

    float acc[8][4] = {};
#pragma unroll 16
    for (int kk = 0; kk < 64; kk++) {
        float a[8];
#pragma unroll
        for (int r = 0; r < 8; r++) a[r] = As[ty * 8 + r][kk];
        float4 b4 = *(float4*)&Bs[kk][tx * 4];
        float b[4] = {b4.x, b4.y, b4.z, b4.w};
#pragma unroll
        for (int r = 0; r < 8; r++)
#pragma unroll
            for (int c = 0; c < 4; c++)
                acc[r][c] = fmaf(a[r], b[c], acc[r][c]);
    }
    float4 bb = *(const float4*)&bde[col0 + tx * 4];
#pragma unroll
    for (int r = 0; r < 8; r++) {
        float4 o = make_float4(acc[r][0] + bb.x, acc[r][1] + bb.y,
                               acc[r][2] + bb.z, acc[r][3] + bb.w);
        *(float4*)&xe[(size_t)(row0 + ty * 8 + r) * Dd + col0 + tx * 4] = o;
    }
}

// ---------------------------------------------------------------------------
// Launch. Output layout (float32, concatenated in reference-return order):
//   x_e [B,D] | x_q [B,D] | z_e [B,L] | z_q [B,L] | z_q_neighbors [B,5,L]
//   | k [B] (cast to float) | z_dist_flat [B,64]
// ---------------------------------------------------------------------------
extern "C" void kernel_launch(void* const* d_in, const int* in_sizes, int n_in,
                              void* d_out, int out_size) {
    const float* x    = (const float*)d_in[0];
    const float* Wenc = (const float*)d_in[1];
    const float* benc = (const float*)d_in[2];
    const float* Wdq  = (const float*)d_in[3];
    const float* bdq  = (const float*)d_in[4];
    const float* Wde  = (const float*)d_in[5];
    const float* bde  = (const float*)d_in[6];
    const float* E    = (const float*)d_in[7];
    float* out = (float*)d_out;

    const size_t OFF_XE = 0;
    const size_t OFF_XQ = (size_t)Bz * Dd;
    const size_t OFF_ZE = 2 * (size_t)Bz * Dd;
    const size_t OFF_ZQ = OFF_ZE + (size_t)Bz * Ld;
    const size_t OFF_NB = OFF_ZQ + (size_t)Bz * Ld;
    const size_t OFF_K  = OFF_NB + (size_t)Bz * 5 * Ld;
    const size_t OFF_ZD = OFF_K + (size_t)Bz;

    k_precompute<<<NC, 256>>>(E, Wdq, bdq);
    k_enc<<<Bz / 64, 256>>>(x, Wenc, benc, out + OFF_ZE);
    k_assign<<<Bz / 256, 256>>>(out + OFF_ZE, E,
                                out + OFF_ZQ, out + OFF_NB,
                                out + OFF_K, out + OFF_ZD);
    k_xq<<<(Bz * (Dd / 4)) / 256, 256>>>(out + OFF_XQ);
    k_dec<<<dim3(Bz / 128, Dd / 64), 256>>>(out + OFF_ZE, Wde, bde, out + OFF_XE);
}